// round 16
// baseline (speedup 1.0000x reference)
#include <cuda_runtime.h>
#include <cuda.h>
#include <cuda_bf16.h>
#include <cstdint>

#define DIM 2048
#define SEQ 2048
#define NHEADS 16
#define HDIM 128

#define GDSMEM 197632                  // 1024 + 2*96KB (tma gemm) / 1024+3*64KB (kv)
#define FDSMEM 164864                  // 1024 + k 2x32KB + v 3x32KB
#define KSPLIT 8

#if defined(__CUDA_ARCH_FEAT_SM103_ALL) || defined(__CUDA_ARCH_FEAT_SM100_ALL) || defined(__CUDA_ARCH_FEAT_SM101_ALL)
#define HAS_TCGEN05 1
#else
#define HAS_TCGEN05 0
#endif

#define MODE_F32   0
#define MODE_HILO  1

// ---------------------------------------------------------------------------
// Scratch (device globals)
// ---------------------------------------------------------------------------
__device__ __nv_bfloat16 g_xhi[(long)SEQ * DIM],  g_xlo[(long)SEQ * DIM];
__device__ __nv_bfloat16 g_Wqhi[(long)DIM * DIM], g_Wqlo[(long)DIM * DIM];
__device__ __nv_bfloat16 g_Wkhi[(long)HDIM * DIM], g_Wklo[(long)HDIM * DIM];
__device__ __nv_bfloat16 g_Wvhi[(long)HDIM * DIM], g_Wvlo[(long)HDIM * DIM];
__device__ __nv_bfloat16 g_Wohi[(long)DIM * DIM], g_Wolo[(long)DIM * DIM];
__device__ __nv_bfloat16 g_qhi[(long)SEQ * DIM],  g_qlo[(long)SEQ * DIM];
__device__ __nv_bfloat16 g_khi[(long)SEQ * HDIM], g_klo[(long)SEQ * HDIM];
__device__ __nv_bfloat16 g_vThi[(long)HDIM * SEQ], g_vTlo[(long)HDIM * SEQ];
__device__ __nv_bfloat16 g_athi[(long)SEQ * DIM], g_atlo[(long)SEQ * DIM];
__device__ float g_kvpart[2][KSPLIT][(long)SEQ * HDIM];

// ---------------------------------------------------------------------------
// PTX helpers
// ---------------------------------------------------------------------------
__device__ __forceinline__ uint32_t cvta_smem(const void* p) {
    uint32_t a;
    asm("{ .reg .u64 t; cvta.to.shared.u64 t, %1; cvt.u32.u64 %0, t; }"
        : "=r"(a) : "l"(p));
    return a;
}
__device__ __forceinline__ void cp16(uint32_t s, const void* g) {
    asm volatile("cp.async.cg.shared.global [%0], [%1], 16;" :: "r"(s), "l"(g));
}
__device__ __forceinline__ void cp_commit() { asm volatile("cp.async.commit_group;"); }
template <int N> __device__ __forceinline__ void cp_wait() {
    asm volatile("cp.async.wait_group %0;" :: "n"(N));
}
__device__ __forceinline__ void tma2d(uint32_t smem, const CUtensorMap* tm,
                                      int x, int y, uint32_t mbar) {
    asm volatile(
        "cp.async.bulk.tensor.2d.shared::cta.global.tile.mbarrier::complete_tx::bytes "
        "[%0], [%1, {%2, %3}], [%4];"
        :: "r"(smem), "l"(tm), "r"(x), "r"(y), "r"(mbar) : "memory");
}
#define MBAR_INIT(mbar, cnt) \
    asm volatile("mbarrier.init.shared.b64 [%0], %1;" :: "r"(mbar), "r"(cnt) : "memory")
#define MBAR_EXPECT(mbar, bytes) \
    asm volatile("mbarrier.arrive.expect_tx.shared.b64 _, [%0], %1;" \
                 :: "r"(mbar), "r"(bytes) : "memory")

__device__ __forceinline__ void mbar_wait(uint32_t mbar, uint32_t parity) {
    uint32_t done;
    asm volatile(
        "{\n .reg .pred p;\n"
        " mbarrier.try_wait.parity.acquire.cta.shared::cta.b64 p, [%1], %2;\n"
        " selp.b32 %0, 1, 0, p;\n}"
        : "=r"(done) : "r"(mbar), "r"(parity) : "memory");
    if (!done) {
        asm volatile(
            "{\n .reg .pred P1;\n"
            "WL_%=:\n"
            " mbarrier.try_wait.parity.acquire.cta.shared::cta.b64 P1, [%0], %1, 0x989680;\n"
            " @P1 bra.uni WD_%=;\n"
            " bra.uni WL_%=;\n"
            "WD_%=:\n}"
            :: "r"(mbar), "r"(parity) : "memory");
    }
}

#if HAS_TCGEN05
__device__ __forceinline__ uint32_t elect1() {
    uint32_t p;
    asm volatile("{\n .reg .pred p;\n elect.sync _|p, 0xFFFFFFFF;\n selp.b32 %0, 1, 0, p;\n}"
                 : "=r"(p));
    return p;
}
#define TC_ALLOC(smem_addr, ncols) \
    asm volatile("tcgen05.alloc.cta_group::1.sync.aligned.shared::cta.b32 [%0], %1;" \
                 :: "r"(smem_addr), "r"(ncols) : "memory")
#define TC_DEALLOC(tmem, ncols) \
    asm volatile("tcgen05.dealloc.cta_group::1.sync.aligned.b32 %0, %1;" \
                 :: "r"(tmem), "r"(ncols))
#define TC_RELINQ() \
    asm volatile("tcgen05.relinquish_alloc_permit.cta_group::1.sync.aligned;")
#define TC_COMMIT(mbar) \
    asm volatile("tcgen05.commit.cta_group::1.mbarrier::arrive::one.shared::cluster.b64 [%0];" \
                 :: "r"(mbar) : "memory")
#define TC_FENCE_AFTER()  asm volatile("tcgen05.fence::after_thread_sync;" ::: "memory")
#define TC_FENCE_BEFORE() asm volatile("tcgen05.fence::before_thread_sync;" ::: "memory")
#define TC_WAIT_LD()      asm volatile("tcgen05.wait::ld.sync.aligned;" ::: "memory")
#define TC_WAIT_ST()      asm volatile("tcgen05.wait::st.sync.aligned;" ::: "memory")

__device__ __forceinline__ void mma_ss(uint32_t d, uint64_t ad, uint64_t bd,
                                       uint32_t idesc, uint32_t en) {
    asm volatile(
        "{\n .reg .pred p;\n setp.ne.u32 p, %4, 0;\n"
        " tcgen05.mma.cta_group::1.kind::f16 [%0], %1, %2, %3, {%5, %5, %5, %5}, p;\n}"
        :: "r"(d), "l"(ad), "l"(bd), "r"(idesc), "r"(en), "r"(0u) : "memory");
}
__device__ __forceinline__ void mma_ts(uint32_t d, uint32_t a, uint64_t bd,
                                       uint32_t idesc, uint32_t en) {
    asm volatile(
        "{\n .reg .pred p;\n setp.ne.u32 p, %4, 0;\n"
        " tcgen05.mma.cta_group::1.kind::f16 [%0], [%1], %2, %3, {%5, %5, %5, %5}, p;\n}"
        :: "r"(d), "r"(a), "l"(bd), "r"(idesc), "r"(en), "r"(0u) : "memory");
}
__device__ __forceinline__ uint64_t make_desc(uint32_t addr) {
    return (uint64_t(2) << 61) | (uint64_t(1) << 46) | (uint64_t(64) << 32) |
           (uint64_t(1) << 16) | ((uint64_t)(addr >> 4) & 0x3FFF);
}

#define LDTM_X32(r, addr) \
    asm volatile( \
        "tcgen05.ld.sync.aligned.32x32b.x32.b32 " \
        "{%0, %1, %2, %3, %4, %5, %6, %7, " \
        " %8, %9, %10, %11, %12, %13, %14, %15, " \
        " %16, %17, %18, %19, %20, %21, %22, %23, " \
        " %24, %25, %26, %27, %28, %29, %30, %31}, [%32];" \
        : "=r"((r)[0]),  "=r"((r)[1]),  "=r"((r)[2]),  "=r"((r)[3]), \
          "=r"((r)[4]),  "=r"((r)[5]),  "=r"((r)[6]),  "=r"((r)[7]), \
          "=r"((r)[8]),  "=r"((r)[9]),  "=r"((r)[10]), "=r"((r)[11]), \
          "=r"((r)[12]), "=r"((r)[13]), "=r"((r)[14]), "=r"((r)[15]), \
          "=r"((r)[16]), "=r"((r)[17]), "=r"((r)[18]), "=r"((r)[19]), \
          "=r"((r)[20]), "=r"((r)[21]), "=r"((r)[22]), "=r"((r)[23]), \
          "=r"((r)[24]), "=r"((r)[25]), "=r"((r)[26]), "=r"((r)[27]), \
          "=r"((r)[28]), "=r"((r)[29]), "=r"((r)[30]), "=r"((r)[31]) \
        : "r"(addr))

#define STTM_X32(addr, r) \
    asm volatile( \
        "tcgen05.st.sync.aligned.32x32b.x32.b32 [%0], " \
        "{%1, %2, %3, %4, %5, %6, %7, %8, " \
        " %9, %10, %11, %12, %13, %14, %15, %16, " \
        " %17, %18, %19, %20, %21, %22, %23, %24, " \
        " %25, %26, %27, %28, %29, %30, %31, %32};" \
        :: "r"(addr), \
           "r"((r)[0]),  "r"((r)[1]),  "r"((r)[2]),  "r"((r)[3]), \
           "r"((r)[4]),  "r"((r)[5]),  "r"((r)[6]),  "r"((r)[7]), \
           "r"((r)[8]),  "r"((r)[9]),  "r"((r)[10]), "r"((r)[11]), \
           "r"((r)[12]), "r"((r)[13]), "r"((r)[14]), "r"((r)[15]), \
           "r"((r)[16]), "r"((r)[17]), "r"((r)[18]), "r"((r)[19]), \
           "r"((r)[20]), "r"((r)[21]), "r"((r)[22]), "r"((r)[23]), \
           "r"((r)[24]), "r"((r)[25]), "r"((r)[26]), "r"((r)[27]), \
           "r"((r)[28]), "r"((r)[29]), "r"((r)[30]), "r"((r)[31]) \
        : "memory")

#define STTM_X16(addr, r) \
    asm volatile( \
        "tcgen05.st.sync.aligned.32x32b.x16.b32 [%0], " \
        "{%1, %2, %3, %4, %5, %6, %7, %8, " \
        " %9, %10, %11, %12, %13, %14, %15, %16};" \
        :: "r"(addr), \
           "r"((r)[0]),  "r"((r)[1]),  "r"((r)[2]),  "r"((r)[3]), \
           "r"((r)[4]),  "r"((r)[5]),  "r"((r)[6]),  "r"((r)[7]), \
           "r"((r)[8]),  "r"((r)[9]),  "r"((r)[10]), "r"((r)[11]), \
           "r"((r)[12]), "r"((r)[13]), "r"((r)[14]), "r"((r)[15]) \
        : "memory")
#endif  // HAS_TCGEN05

// ---------------------------------------------------------------------------
// TMA-fed tensor-core GEMM, 128x256 tile, single-thread mainloop.
// (round-10 proven; UNCHANGED)
// ---------------------------------------------------------------------------
template <int MODE>
__global__ void __launch_bounds__(256) tma_gemm(
    const __grid_constant__ CUtensorMap tmAhi,
    const __grid_constant__ CUtensorMap tmAlo,
    const __grid_constant__ CUtensorMap tmBhi,
    const __grid_constant__ CUtensorMap tmBlo,
    const __nv_bfloat16* __restrict__ Ahi, const __nv_bfloat16* __restrict__ Alo,
    const __nv_bfloat16* __restrict__ Bhi, const __nv_bfloat16* __restrict__ Blo,
    float* __restrict__ Cf, __nv_bfloat16* __restrict__ Chi,
    __nv_bfloat16* __restrict__ Clo, float alpha)
{
    constexpr int NST = 2;
    constexpr int SBYTES = 98304;
    constexpr int NK = DIM / 64;

    extern __shared__ char dsm[];
    const int tid = threadIdx.x;
    const int wid = tid >> 5;
    const int lane = tid & 31;
    const int m0 = blockIdx.y * 128;
    const int n0 = blockIdx.x * 256;

    const uint32_t dbase = (cvta_smem(dsm) + 1023u) & ~1023u;
    float* sm = (float*)(((uintptr_t)dsm + 1023u) & ~(uintptr_t)1023u);

#if HAS_TCGEN05
    __shared__ uint64_t full_bar[NST];
    __shared__ uint64_t mma_bar[NST];
    __shared__ uint64_t end_bar;
    __shared__ uint32_t s_tptr;

    if (wid == 0) { TC_ALLOC(cvta_smem(&s_tptr), 256); TC_RELINQ(); }
    if (tid == 0) {
        for (int s = 0; s < NST; s++) {
            MBAR_INIT(cvta_smem(&full_bar[s]), 1);
            MBAR_INIT(cvta_smem(&mma_bar[s]), 1);
        }
        MBAR_INIT(cvta_smem(&end_bar), 1);
    }
    __syncthreads();
    const uint32_t tmem = s_tptr;
    const uint32_t idesc = (1u << 4) | (1u << 7) | (1u << 10) | (16u << 17) | (8u << 24);

    if (wid == 0 && elect1()) {
        auto issue_stage = [&](int kt, int s) {
            const uint32_t sb = dbase + s * SBYTES;
            const uint32_t fb = cvta_smem(&full_bar[s]);
            MBAR_EXPECT(fb, 98304u);
            tma2d(sb,         &tmAhi, kt * 64, m0, fb);
            tma2d(sb + 16384, &tmAlo, kt * 64, m0, fb);
            tma2d(sb + 32768, &tmBhi, kt * 64, n0, fb);
            tma2d(sb + 65536, &tmBlo, kt * 64, n0, fb);
        };
        issue_stage(0, 0);
        issue_stage(1, 1);

        int phf[NST] = {0, 0}, phm[NST] = {0, 0};
        int s = 0;
        for (int kt = 0; kt < NK; kt++) {
            mbar_wait(cvta_smem(&full_bar[s]), phf[s]); phf[s] ^= 1;
            const uint32_t sb = dbase + s * SBYTES;
#pragma unroll
            for (int t = 0; t < 3; t++) {
                const uint64_t ad = make_desc(sb + (t == 1 ? 16384 : 0));
                const uint32_t bb = sb + 32768 + (t == 2 ? 32768 : 0);
#pragma unroll
                for (int nh = 0; nh < 2; nh++) {
                    const uint64_t bd = make_desc(bb + nh * 16384);
#pragma unroll
                    for (int ki = 0; ki < 4; ki++)
                        mma_ss(tmem + nh * 128, ad + ki * 2, bd + ki * 2, idesc,
                               (kt | t | ki) != 0 ? 1u : 0u);
                }
            }
            TC_COMMIT(cvta_smem(&mma_bar[s]));
            if (kt + NST < NK) {
                mbar_wait(cvta_smem(&mma_bar[s]), phm[s]); phm[s] ^= 1;
                issue_stage(kt + NST, s);
            }
            s ^= 1;
        }
        TC_COMMIT(cvta_smem(&end_bar));
    }

    mbar_wait(cvta_smem(&end_bar), 0);
    TC_FENCE_AFTER();

    if (tid < 128) {
#pragma unroll
        for (int c = 0; c < 8; c++) {
            uint32_t r[32];
            LDTM_X32(r, tmem + c * 32);
            TC_WAIT_LD();
            float* dst = sm + (wid * 32 + lane) * 257 + c * 32;
#pragma unroll
            for (int j = 0; j < 32; j++) dst[j] = __uint_as_float(r[j]);
        }
        TC_FENCE_BEFORE();
    }
    __syncthreads();
    if (wid == 0) TC_DEALLOC(tmem, 256);

    for (int idx = tid; idx < 128 * 256; idx += 256) {
        const int r = idx >> 8, c = idx & 255;
        const float v = sm[r * 257 + c] * alpha;
        const long o = (long)(m0 + r) * DIM + (n0 + c);
        if (MODE == MODE_F32) Cf[o] = v;
        else {
            const __nv_bfloat16 h = __float2bfloat16(v);
            Chi[o] = h;
            Clo[o] = __float2bfloat16(v - __bfloat162float(h));
        }
    }
#else
    for (int idx = tid; idx < 128 * 256; idx += 256) {
        const int r = idx >> 8, c = idx & 255;
        float sum = 0.0f;
        for (int k = 0; k < DIM; k++) {
            const float a = __bfloat162float(Ahi[(long)(m0 + r) * DIM + k]) +
                            __bfloat162float(Alo[(long)(m0 + r) * DIM + k]);
            const float b = __bfloat162float(Bhi[(long)(n0 + c) * DIM + k]) +
                            __bfloat162float(Blo[(long)(n0 + c) * DIM + k]);
            sum += a * b;
        }
        const float v = sum * alpha;
        const long o = (long)(m0 + r) * DIM + (n0 + c);
        if (MODE == MODE_F32) Cf[o] = v;
        else {
            const __nv_bfloat16 h = __float2bfloat16(v);
            Chi[o] = h;
            Clo[o] = __float2bfloat16(v - __bfloat162float(h));
        }
    }
    (void)sm; (void)dbase;
#endif
}

// ---------------------------------------------------------------------------
// Split-K k/v projection (round-9 proven; UNCHANGED)
// ---------------------------------------------------------------------------
__global__ void __launch_bounds__(256) kv_gemm(
    const __nv_bfloat16* __restrict__ xhi, const __nv_bfloat16* __restrict__ xlo,
    const __nv_bfloat16* __restrict__ Wkhi, const __nv_bfloat16* __restrict__ Wklo,
    const __nv_bfloat16* __restrict__ Wvhi, const __nv_bfloat16* __restrict__ Wvlo,
    float* __restrict__ part)
{
    constexpr int NST = 3;
    constexpr int SBYTES = 65536;
    constexpr int KC = DIM / KSPLIT;
    extern __shared__ char dsm[];
    const int tid = threadIdx.x;
    const int wid = tid >> 5;
    const int lane = tid & 31;
    const int ks = blockIdx.x;
    const int m0 = blockIdx.y * 128;
    const int z = blockIdx.z;
    const long kOff = (long)ks * KC;

    const __nv_bfloat16* Bhi = z ? Wvhi : Wkhi;
    const __nv_bfloat16* Blo = z ? Wvlo : Wklo;
    float* out = part + ((long)z * KSPLIT + ks) * ((long)SEQ * HDIM) + (long)m0 * HDIM;

    const uint32_t dbase = (cvta_smem(dsm) + 1023u) & ~1023u;
    float* sm = (float*)(((uintptr_t)dsm + 1023u) & ~(uintptr_t)1023u);

    const int nk = KC / 64;

    auto load_stage = [&](int kt, int s) {
        const long k0 = kOff + (long)kt * 64;
        const uint32_t sb = dbase + s * SBYTES;
#pragma unroll
        for (int i = 0; i < 16; i++) {
            const int idx = tid + i * 256;
            const int partn = idx >> 10;
            const int r = (idx >> 3) & 127;
            const int c16 = idx & 7;
            const uint32_t off = r * 128 + c16 * 16;
            const uint32_t sw = off ^ ((off >> 3) & 0x70);
            const __nv_bfloat16* src;
            long grow;
            if (partn == 0)      { src = xhi; grow = (long)(m0 + r) * DIM; }
            else if (partn == 1) { src = xlo; grow = (long)(m0 + r) * DIM; }
            else if (partn == 2) { src = Bhi; grow = (long)r * DIM; }
            else                 { src = Blo; grow = (long)r * DIM; }
            cp16(sb + partn * 16384 + sw, src + grow + k0 + c16 * 8);
        }
        cp_commit();
    };

#if HAS_TCGEN05
    __shared__ uint64_t s_bar[NST + 1];
    __shared__ uint32_t s_tptr;

    if (wid == 0) { TC_ALLOC(cvta_smem(&s_tptr), 128); TC_RELINQ(); }
    if (tid == 0)
        for (int s = 0; s < NST + 1; s++) MBAR_INIT(cvta_smem(&s_bar[s]), 1);
    __syncthreads();
    const uint32_t tmem = s_tptr;

    for (int t = 0; t < NST; t++) load_stage(t, t);

    const uint32_t idesc = (1u << 4) | (1u << 7) | (1u << 10) | (16u << 17) | (8u << 24);
    int ph[NST];
#pragma unroll
    for (int s = 0; s < NST; s++) ph[s] = 0;

    int s = 0;
    for (int kt = 0; kt < nk; kt++) {
        cp_wait<NST - 1>();
        __syncthreads();
        asm volatile("fence.proxy.async.shared::cta;" ::: "memory");
        if (wid == 0) {
            if (elect1()) {
                const uint32_t sb = dbase + s * SBYTES;
#pragma unroll
                for (int t = 0; t < 3; t++) {
                    const uint64_t ad = make_desc(sb + (t == 1 ? 1 : 0) * 16384);
                    const uint64_t bd = make_desc(sb + (t == 2 ? 3 : 2) * 16384);
#pragma unroll
                    for (int ki = 0; ki < 4; ki++)
                        mma_ss(tmem, ad + ki * 2, bd + ki * 2, idesc,
                               (kt | t | ki) != 0 ? 1u : 0u);
                }
                TC_COMMIT(cvta_smem(&s_bar[s]));
            }
        }
        if (kt + NST < nk) {
            mbar_wait(cvta_smem(&s_bar[s]), ph[s]);
            ph[s] ^= 1;
            load_stage(kt + NST, s);
        } else {
            cp_commit();
        }
        s++; if (s == NST) s = 0;
    }

    if (wid == 0) { if (elect1()) TC_COMMIT(cvta_smem(&s_bar[NST])); }
    mbar_wait(cvta_smem(&s_bar[NST]), 0);
    TC_FENCE_AFTER();

    if (tid < 128) {
#pragma unroll
        for (int c = 0; c < 4; c++) {
            uint32_t r[32];
            LDTM_X32(r, tmem + c * 32);
            TC_WAIT_LD();
            float* dst = sm + (wid * 32 + lane) * 129 + c * 32;
#pragma unroll
            for (int j = 0; j < 32; j++) dst[j] = __uint_as_float(r[j]);
        }
        TC_FENCE_BEFORE();
    }
    __syncthreads();
    if (wid == 0) TC_DEALLOC(tmem, 128);

    for (int idx = tid; idx < 16384; idx += 256) {
        const int r = idx >> 7, c = idx & 127;
        out[(long)r * HDIM + c] = sm[r * 129 + c];
    }
#else
    for (int e = tid; e < 16384; e += 256) {
        const int r = e >> 7, c = e & 127;
        float sum = 0.0f;
        for (int kk = 0; kk < KC; kk++) {
            const long ik = kOff + kk;
            const float a = __bfloat162float(xhi[(long)(m0 + r) * DIM + ik]) +
                            __bfloat162float(xlo[(long)(m0 + r) * DIM + ik]);
            const float b = __bfloat162float(Bhi[(long)c * DIM + ik]) +
                            __bfloat162float(Blo[(long)c * DIM + ik]);
            sum += a * b;
        }
        out[(long)r * HDIM + c] = sum;
    }
#endif
}

// ---------------------------------------------------------------------------
__global__ void __launch_bounds__(256) kv_reduce(
    const float* __restrict__ part,
    __nv_bfloat16* __restrict__ khi, __nv_bfloat16* __restrict__ klo,
    __nv_bfloat16* __restrict__ vThi, __nv_bfloat16* __restrict__ vTlo)
{
    const long idx = (long)blockIdx.x * 256 + threadIdx.x;
    const int sel = (int)(idx >> 18);
    const long i = idx & 262143;
    const float* p = part + (long)sel * KSPLIT * SEQ * HDIM + i;
    float sum = 0.0f;
#pragma unroll
    for (int s = 0; s < KSPLIT; s++) sum += p[(long)s * SEQ * HDIM];
    const __nv_bfloat16 h = __float2bfloat16(sum);
    const __nv_bfloat16 l = __float2bfloat16(sum - __bfloat162float(h));
    if (sel == 0) {
        khi[i] = h; klo[i] = l;
    } else {
        const long m = i >> 7, c = i & 127;
        vThi[c * SEQ + m] = h; vTlo[c * SEQ + m] = l;
    }
}

// ---------------------------------------------------------------------------
// Fused flash attention per (head, q-tile 128) — PIPELINED, kv-tile 64.
// TMEM (448 of 512): q hi/lo 0-127 | P hi/lo 128-191 | S0 192-255 |
//                    S1 256-319 | O 320-447
// smem: k double 2x32KB @0 | v triple 3x32KB @64KB   (q stays in TMEM)
// Pipeline: after S(j) wait, issue S(j+1) into the other S buffer so it
// overlaps epilogue(j)+PV(j) on the tensor pipe. v triple-buffered so
// v(j+2) prefetch never waits on PV(j).
// ---------------------------------------------------------------------------
__global__ void __launch_bounds__(256) fused_attn(
    const __nv_bfloat16* __restrict__ qhi, const __nv_bfloat16* __restrict__ qlo,
    const __nv_bfloat16* __restrict__ khi, const __nv_bfloat16* __restrict__ klo,
    const __nv_bfloat16* __restrict__ vThi, const __nv_bfloat16* __restrict__ vTlo,
    __nv_bfloat16* __restrict__ ohi, __nv_bfloat16* __restrict__ olo)
{
    extern __shared__ char dsm[];
    const int tid = threadIdx.x;
    const int wid = tid >> 5;
    const int lane = tid & 31;
    const int h = blockIdx.x;
    const int m0 = blockIdx.y * 128;
    const float scale = 0.08838834764831845f;
    const float CSH = 6.0f;

#if HAS_TCGEN05
    __shared__ uint64_t s_bar[2];     // per S-buffer
    __shared__ uint64_t pv_bar;
    __shared__ uint32_t s_tptr;
    __shared__ float rs[128];
    const uint32_t dbase = (cvta_smem(dsm) + 1023u) & ~1023u;
    const uint32_t vbase = dbase + 65536;

    if (wid == 0) { TC_ALLOC(cvta_smem(&s_tptr), 512); TC_RELINQ(); }
    if (tid == 0) {
        MBAR_INIT(cvta_smem(&s_bar[0]), 1);
        MBAR_INIT(cvta_smem(&s_bar[1]), 1);
        MBAR_INIT(cvta_smem(&pv_bar), 1);
    }
    if (tid < 128) rs[tid] = 0.0f;
    __syncthreads();
    const uint32_t tmem = s_tptr;
    const uint32_t tQ = tmem;          // 128 cols (hi 0-63, lo 64-127)
    const uint32_t tP = tmem + 128;    // 64 cols (hi 0-31, lo 32-63)
    const uint32_t tS = tmem + 192;    // 2 x 64 cols
    const uint32_t tO = tmem + 320;    // 128 cols

    const int sp = wid & 3;
    const int half = wid >> 2;
    const uint32_t woff = (uint32_t)sp << 21;

    // k tile: 64 kv-rows x 128 d; buffer (32KB) = khi_c0 8K | khi_c1 8K |
    // klo_c0 8K | klo_c1 8K. 2048 cp16 = 8/thread.
    auto load_k = [&](int j, int b) {
#pragma unroll
        for (int i = 0; i < 8; i++) {
            const int idx = tid + i * 256;
            const int part = idx >> 9;          // 0..3
            const int r = (idx >> 3) & 63;
            const int c16 = idx & 7;
            const __nv_bfloat16* src = (part < 2) ? khi : klo;
            const uint32_t off = r * 128 + c16 * 16;
            cp16(dbase + b * 32768 + part * 8192 + (off ^ ((off >> 3) & 0x70)),
                 src + (long)(j * 64 + r) * HDIM + (part & 1) * 64 + c16 * 8);
        }
        cp_commit();
    };
    // v tile: 128 d-rows x 64 kv; buffer (32KB) = vhi 16K | vlo 16K.
    auto load_v = [&](int j, int b) {
#pragma unroll
        for (int i = 0; i < 8; i++) {
            const int idx = tid + i * 256;
            const int part = idx >> 10;         // 0: hi, 1: lo
            const int r = (idx >> 3) & 127;
            const int c16 = idx & 7;
            const __nv_bfloat16* src = part ? vTlo : vThi;
            const uint32_t off = r * 128 + c16 * 16;
            cp16(vbase + b * 32768 + part * 16384 + (off ^ ((off >> 3) & 0x70)),
                 src + (long)r * SEQ + j * 64 + c16 * 8);
        }
        cp_commit();
    };

    // prologue loads: k0/v0 (buf 0), k1/v1 (buf 1)
    load_k(0, 0); load_v(0, 0);
    load_k(1, 1); load_v(1, 1);

    // q -> TMEM (TS A-operand), unchanged
    float rowsum = 0.0f;
    if (tid < 128) {
        const uint32_t qoff = (uint32_t)wid << 21;
        const uint4* s4h = (const uint4*)(qhi + (long)(m0 + tid) * DIM + h * HDIM);
        const uint4* s4l = (const uint4*)(qlo + (long)(m0 + tid) * DIM + h * HDIM);
        uint32_t rq[32];
#pragma unroll
        for (int hf = 0; hf < 2; hf++) {
#pragma unroll
            for (int i = 0; i < 8; i++) {
                uint4 t4 = s4h[hf * 8 + i];
                rq[i * 4] = t4.x; rq[i * 4 + 1] = t4.y; rq[i * 4 + 2] = t4.z; rq[i * 4 + 3] = t4.w;
            }
            STTM_X32(tQ + hf * 32 + qoff, rq);
        }
#pragma unroll
        for (int hf = 0; hf < 2; hf++) {
#pragma unroll
            for (int i = 0; i < 8; i++) {
                uint4 t4 = s4l[hf * 8 + i];
                rq[i * 4] = t4.x; rq[i * 4 + 1] = t4.y; rq[i * 4 + 2] = t4.z; rq[i * 4 + 3] = t4.w;
            }
            STTM_X32(tQ + 64 + hf * 32 + qoff, rq);
        }
        TC_WAIT_ST();
        TC_FENCE_BEFORE();
    }
    __syncthreads();

    // S idesc: M=128, N=64; PV idesc: M=128, N=128
    const uint32_t idescS  = (1u << 4) | (1u << 7) | (1u << 10) | (8u << 17)  | (8u << 24);
    const uint32_t idescPV = (1u << 4) | (1u << 7) | (1u << 10) | (16u << 17) | (8u << 24);

    // S issue helper (warp0-elect context): buffer b = jj&1 uses k buffer b
    auto issue_S = [&](int jj) {
        const int b = jj & 1;
        const uint32_t dst = tS + b * 64;
#pragma unroll
        for (int t = 0; t < 3; t++) {
            const uint32_t aoff = (t == 1) ? 64u : 0u;
            const uint32_t kb = dbase + b * 32768 + (t == 2 ? 16384u : 0u);
#pragma unroll
            for (int c = 0; c < 2; c++) {
                const uint64_t bd = make_desc(kb + c * 8192);
#pragma unroll
                for (int ki = 0; ki < 4; ki++)
                    mma_ts(dst, tQ + aoff + c * 32 + ki * 8, bd + ki * 2, idescS,
                           (t | c | ki) != 0 ? 1u : 0u);
            }
        }
        TC_COMMIT(cvta_smem(&s_bar[b]));
    };

    // initial S(0): wait k0/v0 fills (first 2 of 4 committed groups)
    cp_wait<2>();
    __syncthreads();
    asm volatile("fence.proxy.async.shared::cta;" ::: "memory");
    if (wid == 0 && elect1()) {
        TC_FENCE_AFTER();
        issue_S(0);
    }

    int ph_s[2] = {0, 0};
    int ph_pv = 0;

    for (int j = 0; j < 32; j++) {
        const int b = j & 1;
        // S(j) done
        mbar_wait(cvta_smem(&s_bar[b]), ph_s[b]); ph_s[b] ^= 1;
        TC_FENCE_AFTER();

        // all outstanding loads (k(j+1), v(j+1)) complete
        cp_wait<0>();
        __syncthreads();
        asm volatile("fence.proxy.async.shared::cta;" ::: "memory");

        // issue S(j+1) into the other S buffer — overlaps epilogue + PV below
        if (j + 1 < 32 && wid == 0 && elect1()) {
            TC_FENCE_AFTER();
            issue_S(j + 1);
        }

        // PV(j-1) done before overwriting P
        if (j > 0) { mbar_wait(cvta_smem(&pv_bar), ph_pv); ph_pv ^= 1; }
        TC_FENCE_AFTER();

        // epilogue on S(j): 8 warps, warp (sp, half) reads S cols half*32..+32
        {
            uint32_t r[32];
            LDTM_X32(r, tS + b * 64 + half * 32);
            TC_WAIT_LD();
            uint32_t phl[16], pll[16];
#pragma unroll
            for (int i = 0; i < 16; i++) {
                const float e0 = __expf(__uint_as_float(r[2 * i]) * scale - CSH);
                const float e1 = __expf(__uint_as_float(r[2 * i + 1]) * scale - CSH);
                rowsum += e0 + e1;
                const __nv_bfloat16 h0 = __float2bfloat16(e0);
                const __nv_bfloat16 h1 = __float2bfloat16(e1);
                const __nv_bfloat16 l0 = __float2bfloat16(e0 - __bfloat162float(h0));
                const __nv_bfloat16 l1 = __float2bfloat16(e1 - __bfloat162float(h1));
                __nv_bfloat162 hp(h0, h1), lp(l0, l1);
                phl[i] = *(uint32_t*)&hp;
                pll[i] = *(uint32_t*)&lp;
            }
            STTM_X16(tP + half * 16 + woff, phl);
            STTM_X16(tP + 32 + half * 16 + woff, pll);
            TC_WAIT_ST();
            TC_FENCE_BEFORE();
        }
        __syncthreads();

        // PV(j): O += P(j) @ v(j)   (v buffer j%3; 3 terms x 4 ksteps)
        if (wid == 0 && elect1()) {
            TC_FENCE_AFTER();
            const uint32_t vb = vbase + (j % 3) * 32768;
#pragma unroll
            for (int t = 0; t < 3; t++) {
                const uint32_t aoff = (t == 1) ? 32u : 0u;
                const uint64_t bd = make_desc(vb + (t == 2 ? 16384u : 0u));
#pragma unroll
                for (int ki = 0; ki < 4; ki++)
                    mma_ts(tO, tP + aoff + ki * 8, bd + ki * 2, idescPV,
                           (j | t | ki) != 0 ? 1u : 0u);
            }
            TC_COMMIT(cvta_smem(&pv_bar));
        }

        // prefetch j+2: k buffer (j+2)&1 freed by S(j); v buffer (j+2)%3
        // held v(j-1), whose PV(j-1) was waited above.
        if (j + 2 < 32) {
            load_k(j + 2, (j + 2) & 1);
            load_v(j + 2, (j + 2) % 3);
        }
    }
    mbar_wait(cvta_smem(&pv_bar), ph_pv);
    TC_FENCE_AFTER();

    atomicAdd(&rs[sp * 32 + lane], rowsum);
    __syncthreads();

    // final epilogue: O / rowsum -> bf16 hi/lo (all 8 warps; 4 O slabs)
    {
        const float inv = 1.0f / rs[sp * 32 + lane];
        const long obase = (long)(m0 + sp * 32 + lane) * DIM + h * HDIM;
#pragma unroll
        for (int ss = 0; ss < 2; ss++) {
            const int slab = half * 2 + ss;
            uint32_t r[32];
            LDTM_X32(r, tO + slab * 32);
            TC_WAIT_LD();
            uint32_t hb[16], lb[16];
#pragma unroll
            for (int i = 0; i < 16; i++) {
                const float v0 = __uint_as_float(r[2 * i]) * inv;
                const float v1 = __uint_as_float(r[2 * i + 1]) * inv;
                const __nv_bfloat16 h0 = __float2bfloat16(v0);
                const __nv_bfloat16 h1 = __float2bfloat16(v1);
                const __nv_bfloat16 l0 = __float2bfloat16(v0 - __bfloat162float(h0));
                const __nv_bfloat16 l1 = __float2bfloat16(v1 - __bfloat162float(h1));
                __nv_bfloat162 hp(h0, h1), lp(l0, l1);
                hb[i] = *(uint32_t*)&hp;
                lb[i] = *(uint32_t*)&lp;
            }
            uint4* dh = (uint4*)(ohi + obase + slab * 32);
            uint4* dl = (uint4*)(olo + obase + slab * 32);
#pragma unroll
            for (int i = 0; i < 4; i++) {
                dh[i] = make_uint4(hb[4 * i], hb[4 * i + 1], hb[4 * i + 2], hb[4 * i + 3]);
                dl[i] = make_uint4(lb[4 * i], lb[4 * i + 1], lb[4 * i + 2], lb[4 * i + 3]);
            }
        }
    }
    __syncthreads();
    if (wid == 0) TC_DEALLOC(tmem, 512);

#else
    // fp32 fallback (compile-only; the sm_103a cubin is selected at runtime)
    float* qsm = (float*)dsm;
    float* ksm = qsm + 16384;
    float* vsm = ksm + 16384;
    __shared__ float rsf[128];
    const int tr = tid >> 4, tc = tid & 15;
    float o[8][8];
#pragma unroll
    for (int i = 0; i < 8; i++)
#pragma unroll
        for (int j = 0; j < 8; j++) o[i][j] = 0.0f;
    if (tid < 128) rsf[tid] = 0.0f;

    for (int i = tid; i < 16384; i += 256) {
        const int r = i >> 7, c = i & 127;
        const long g = (long)(m0 + r) * DIM + h * HDIM + c;
        qsm[i] = __bfloat162float(qhi[g]) + __bfloat162float(qlo[g]);
    }
    __syncthreads();

    for (int j = 0; j < 16; j++) {
        for (int i = tid; i < 16384; i += 256) {
            const int r = i >> 7, c = i & 127;
            const long gk = (long)(j * 128 + r) * HDIM + c;
            ksm[i] = __bfloat162float(khi[gk]) + __bfloat162float(klo[gk]);
            const long gv = (long)c * SEQ + j * 128 + r;
            vsm[i] = __bfloat162float(vThi[gv]) + __bfloat162float(vTlo[gv]);
        }
        __syncthreads();
        float sacc[8][8];
#pragma unroll
        for (int i = 0; i < 8; i++)
#pragma unroll
            for (int j2 = 0; j2 < 8; j2++) sacc[i][j2] = 0.0f;
        for (int kk = 0; kk < 128; kk++) {
            float ar[8], br[8];
#pragma unroll
            for (int i = 0; i < 8; i++) ar[i] = qsm[(tr * 8 + i) * 128 + kk];
#pragma unroll
            for (int i = 0; i < 8; i++) br[i] = ksm[(tc * 8 + i) * 128 + kk];
#pragma unroll
            for (int i = 0; i < 8; i++)
#pragma unroll
                for (int j2 = 0; j2 < 8; j2++) sacc[i][j2] += ar[i] * br[j2];
        }
        __syncthreads();
#pragma unroll
        for (int i = 0; i < 8; i++) {
            float rl = 0.0f;
#pragma unroll
            for (int j2 = 0; j2 < 8; j2++) {
                const float p = __expf(sacc[i][j2] * scale - CSH);
                ksm[(tr * 8 + i) * 128 + tc * 8 + j2] = p;
                rl += p;
            }
            atomicAdd(&rsf[tr * 8 + i], rl);
        }
        __syncthreads();
        for (int kk = 0; kk < 128; kk++) {
            float pr[8], vr[8];
#pragma unroll
            for (int i = 0; i < 8; i++) pr[i] = ksm[(tr * 8 + i) * 128 + kk];
#pragma unroll
            for (int i = 0; i < 8; i++) vr[i] = vsm[kk * 128 + tc * 8 + i];
#pragma unroll
            for (int i = 0; i < 8; i++)
#pragma unroll
                for (int j2 = 0; j2 < 8; j2++) o[i][j2] += pr[i] * vr[j2];
        }
        __syncthreads();
    }
#pragma unroll
    for (int i = 0; i < 8; i++) {
        const int row = tr * 8 + i;
        const float inv = 1.0f / rsf[row];
#pragma unroll
        for (int j2 = 0; j2 < 8; j2++) {
            const float v = o[i][j2] * inv;
            const long g = (long)(m0 + row) * DIM + h * HDIM + tc * 8 + j2;
            const __nv_bfloat16 hh = __float2bfloat16(v);
            ohi[g] = hh;
            olo[g] = __float2bfloat16(v - __bfloat162float(hh));
        }
    }
#endif
}

// ---------------------------------------------------------------------------
__global__ void __launch_bounds__(256) split_all(
    const float* __restrict__ x,  const float* __restrict__ Wq,
    const float* __restrict__ Wk, const float* __restrict__ Wv,
    const float* __restrict__ Wo,
    __nv_bfloat16* __restrict__ xhi,  __nv_bfloat16* __restrict__ xlo,
    __nv_bfloat16* __restrict__ Wqhi, __nv_bfloat16* __restrict__ Wqlo,
    __nv_bfloat16* __restrict__ Wkhi, __nv_bfloat16* __restrict__ Wklo,
    __nv_bfloat16* __restrict__ Wvhi, __nv_bfloat16* __restrict__ Wvlo,
    __nv_bfloat16* __restrict__ Wohi, __nv_bfloat16* __restrict__ Wolo)
{
    const int bid = blockIdx.x;
    const float* src;
    __nv_bfloat16 *hi, *lo;
    long base;
    if (bid < 4096)      { src = x;  hi = xhi;  lo = xlo;  base = bid; }
    else if (bid < 8192) { src = Wq; hi = Wqhi; lo = Wqlo; base = bid - 4096; }
    else if (bid < 8448) { src = Wk; hi = Wkhi; lo = Wklo; base = bid - 8192; }
    else if (bid < 8704) { src = Wv; hi = Wvhi; lo = Wvlo; base = bid - 8448; }
    else                 { src = Wo; hi = Wohi; lo = Wolo; base = bid - 8704; }

    const long i = base * 256 + threadIdx.x;
    const float4 v = reinterpret_cast<const float4*>(src)[i];
    __nv_bfloat16 h0 = __float2bfloat16(v.x);
    __nv_bfloat16 h1 = __float2bfloat16(v.y);
    __nv_bfloat16 h2 = __float2bfloat16(v.z);
    __nv_bfloat16 h3 = __float2bfloat16(v.w);
    __nv_bfloat162* hi2 = reinterpret_cast<__nv_bfloat162*>(hi);
    __nv_bfloat162* lo2 = reinterpret_cast<__nv_bfloat162*>(lo);
    hi2[i * 2 + 0] = __nv_bfloat162(h0, h1);
    hi2[i * 2 + 1] = __nv_bfloat162(h2, h3);
    lo2[i * 2 + 0] = __nv_bfloat162(__float2bfloat16(v.x - __bfloat162float(h0)),
                                    __float2bfloat16(v.y - __bfloat162float(h1)));
    lo2[i * 2 + 1] = __nv_bfloat162(__float2bfloat16(v.z - __bfloat162float(h2)),
                                    __float2bfloat16(v.w - __bfloat162float(h3)));
}

// ---------------------------------------------------------------------------
typedef CUresult (*PFN_tmEncode)(
    CUtensorMap*, CUtensorMapDataType, cuuint32_t, void*,
    const cuuint64_t*, const cuuint64_t*, const cuuint32_t*, const cuuint32_t*,
    CUtensorMapInterleave, CUtensorMapSwizzle, CUtensorMapL2promotion,
    CUtensorMapFloatOOBfill);

static void make_tm(PFN_tmEncode enc, CUtensorMap* tm, void* ptr, uint32_t boxRows) {
    cuuint64_t dims[2]    = {DIM, DIM};
    cuuint64_t strides[1] = {DIM * 2};
    cuuint32_t box[2]     = {64, boxRows};
    cuuint32_t es[2]      = {1, 1};
    enc(tm, CU_TENSOR_MAP_DATA_TYPE_BFLOAT16, 2, ptr, dims, strides, box, es,
        CU_TENSOR_MAP_INTERLEAVE_NONE, CU_TENSOR_MAP_SWIZZLE_128B,
        CU_TENSOR_MAP_L2_PROMOTION_L2_128B, CU_TENSOR_MAP_FLOAT_OOB_FILL_NONE);
}

extern "C" void kernel_launch(void* const* d_in, const int* in_sizes, int n_in,
                              void* d_out, int out_size)
{
    const float* x  = (const float*)d_in[0];
    const float* Wq = (const float*)d_in[1];
    const float* Wk = (const float*)d_in[2];
    const float* Wv = (const float*)d_in[3];
    const float* Wo = (const float*)d_in[4];
    float* out = (float*)d_out;

    __nv_bfloat16 *xhi, *xlo, *Wqhi, *Wqlo, *Wkhi, *Wklo, *Wvhi, *Wvlo, *Wohi, *Wolo;
    __nv_bfloat16 *qhi, *qlo, *khi, *klo, *vThi, *vTlo, *athi, *atlo;
    float* kvpart;
    cudaGetSymbolAddress((void**)&xhi, g_xhi);   cudaGetSymbolAddress((void**)&xlo, g_xlo);
    cudaGetSymbolAddress((void**)&Wqhi, g_Wqhi); cudaGetSymbolAddress((void**)&Wqlo, g_Wqlo);
    cudaGetSymbolAddress((void**)&Wkhi, g_Wkhi); cudaGetSymbolAddress((void**)&Wklo, g_Wklo);
    cudaGetSymbolAddress((void**)&Wvhi, g_Wvhi); cudaGetSymbolAddress((void**)&Wvlo, g_Wvlo);
    cudaGetSymbolAddress((void**)&Wohi, g_Wohi); cudaGetSymbolAddress((void**)&Wolo, g_Wolo);
    cudaGetSymbolAddress((void**)&qhi, g_qhi);   cudaGetSymbolAddress((void**)&qlo, g_qlo);
    cudaGetSymbolAddress((void**)&khi, g_khi);   cudaGetSymbolAddress((void**)&klo, g_klo);
    cudaGetSymbolAddress((void**)&vThi, g_vThi); cudaGetSymbolAddress((void**)&vTlo, g_vTlo);
    cudaGetSymbolAddress((void**)&athi, g_athi); cudaGetSymbolAddress((void**)&atlo, g_atlo);
    cudaGetSymbolAddress((void**)&kvpart, g_kvpart);

    void* encPtr = nullptr;
    cudaDriverEntryPointQueryResult st;
    cudaGetDriverEntryPoint("cuTensorMapEncodeTiled", &encPtr, cudaEnableDefault, &st);
    PFN_tmEncode enc = (PFN_tmEncode)encPtr;

    CUtensorMap tmXhi, tmXlo, tmWqhi, tmWqlo, tmAThi, tmATlo, tmWohi, tmWolo;
    make_tm(enc, &tmXhi,  xhi,  128);
    make_tm(enc, &tmXlo,  xlo,  128);
    make_tm(enc, &tmWqhi, Wqhi, 256);
    make_tm(enc, &tmWqlo, Wqlo, 256);
    make_tm(enc, &tmAThi, athi, 128);
    make_tm(enc, &tmATlo, atlo, 128);
    make_tm(enc, &tmWohi, Wohi, 256);
    make_tm(enc, &tmWolo, Wolo, 256);

    cudaFuncSetAttribute((void*)tma_gemm<MODE_HILO>, cudaFuncAttributeMaxDynamicSharedMemorySize, GDSMEM);
    cudaFuncSetAttribute((void*)tma_gemm<MODE_F32>,  cudaFuncAttributeMaxDynamicSharedMemorySize, GDSMEM);
    cudaFuncSetAttribute((void*)kv_gemm,    cudaFuncAttributeMaxDynamicSharedMemorySize, GDSMEM);
    cudaFuncSetAttribute((void*)fused_attn, cudaFuncAttributeMaxDynamicSharedMemorySize, FDSMEM);

    // 0) splits
    split_all<<<12800, 256>>>(x, Wq, Wk, Wv, Wo,
                              xhi, xlo, Wqhi, Wqlo, Wkhi, Wklo,
                              Wvhi, Wvlo, Wohi, Wolo);

    // 1) k & vT projections (split-K) + reduce
    kv_gemm<<<dim3(KSPLIT, SEQ / 128, 2), 256, GDSMEM>>>(
        xhi, xlo, Wkhi, Wklo, Wvhi, Wvlo, kvpart);
    kv_reduce<<<2048, 256>>>(kvpart, khi, klo, vThi, vTlo);

    // 2) q = x @ Wq^T (TMA-fed)
    tma_gemm<MODE_HILO><<<dim3(DIM / 256, SEQ / 128), 256, GDSMEM>>>(
        tmXhi, tmXlo, tmWqhi, tmWqlo,
        xhi, xlo, Wqhi, Wqlo,
        nullptr, qhi, qlo, 1.0f);

    // 3) fused attention (pipelined, kv-tile 64)
    fused_attn<<<dim3(NHEADS, SEQ / 128), 256, FDSMEM>>>(
        qhi, qlo, khi, klo, vThi, vTlo, athi, atlo);

    // 4) out = attn @ Wo^T (TMA-fed)
    tma_gemm<MODE_F32><<<dim3(DIM / 256, SEQ / 128), 256, GDSMEM>>>(
        tmAThi, tmATlo, tmWohi, tmWolo,
        athi, atlo, Wohi, Wolo,
        out, nullptr, nullptr, 1.0f);
}

// round 17
// speedup vs baseline: 1.0111x; 1.0111x over previous
#include <cuda_runtime.h>
#include <cuda.h>
#include <cuda_bf16.h>
#include <cstdint>

#define DIM 2048
#define SEQ 2048
#define NHEADS 16
#define HDIM 128

#define GDSMEM 197632                  // 1024 + 2*96KB (tma gemm) / 1024+3*64KB (kv)
#define FDSMEM (1024 + 3 * 65536)
#define KSPLIT 8

#if defined(__CUDA_ARCH_FEAT_SM103_ALL) || defined(__CUDA_ARCH_FEAT_SM100_ALL) || defined(__CUDA_ARCH_FEAT_SM101_ALL)
#define HAS_TCGEN05 1
#else
#define HAS_TCGEN05 0
#endif

#define MODE_F32   0
#define MODE_HILO  1

// ---------------------------------------------------------------------------
// Scratch (device globals)
// ---------------------------------------------------------------------------
__device__ __nv_bfloat16 g_xhi[(long)SEQ * DIM],  g_xlo[(long)SEQ * DIM];
__device__ __nv_bfloat16 g_Wqhi[(long)DIM * DIM], g_Wqlo[(long)DIM * DIM];
__device__ __nv_bfloat16 g_Wkhi[(long)HDIM * DIM], g_Wklo[(long)HDIM * DIM];
__device__ __nv_bfloat16 g_Wvhi[(long)HDIM * DIM], g_Wvlo[(long)HDIM * DIM];
__device__ __nv_bfloat16 g_Wohi[(long)DIM * DIM], g_Wolo[(long)DIM * DIM];
__device__ __nv_bfloat16 g_qhi[(long)SEQ * DIM],  g_qlo[(long)SEQ * DIM];
__device__ __nv_bfloat16 g_khi[(long)SEQ * HDIM], g_klo[(long)SEQ * HDIM];
__device__ __nv_bfloat16 g_vThi[(long)HDIM * SEQ], g_vTlo[(long)HDIM * SEQ];
__device__ __nv_bfloat16 g_athi[(long)SEQ * DIM], g_atlo[(long)SEQ * DIM];
__device__ float g_kvpart[2][KSPLIT][(long)SEQ * HDIM];

// ---------------------------------------------------------------------------
// PTX helpers
// ---------------------------------------------------------------------------
__device__ __forceinline__ uint32_t cvta_smem(const void* p) {
    uint32_t a;
    asm("{ .reg .u64 t; cvta.to.shared.u64 t, %1; cvt.u32.u64 %0, t; }"
        : "=r"(a) : "l"(p));
    return a;
}
__device__ __forceinline__ void cp16(uint32_t s, const void* g) {
    asm volatile("cp.async.cg.shared.global [%0], [%1], 16;" :: "r"(s), "l"(g));
}
__device__ __forceinline__ void cp_commit() { asm volatile("cp.async.commit_group;"); }
template <int N> __device__ __forceinline__ void cp_wait() {
    asm volatile("cp.async.wait_group %0;" :: "n"(N));
}
__device__ __forceinline__ void tma2d(uint32_t smem, const CUtensorMap* tm,
                                      int x, int y, uint32_t mbar) {
    asm volatile(
        "cp.async.bulk.tensor.2d.shared::cta.global.tile.mbarrier::complete_tx::bytes "
        "[%0], [%1, {%2, %3}], [%4];"
        :: "r"(smem), "l"(tm), "r"(x), "r"(y), "r"(mbar) : "memory");
}
#define MBAR_INIT(mbar, cnt) \
    asm volatile("mbarrier.init.shared.b64 [%0], %1;" :: "r"(mbar), "r"(cnt) : "memory")
#define MBAR_EXPECT(mbar, bytes) \
    asm volatile("mbarrier.arrive.expect_tx.shared.b64 _, [%0], %1;" \
                 :: "r"(mbar), "r"(bytes) : "memory")

__device__ __forceinline__ void mbar_wait(uint32_t mbar, uint32_t parity) {
    uint32_t done;
    asm volatile(
        "{\n .reg .pred p;\n"
        " mbarrier.try_wait.parity.acquire.cta.shared::cta.b64 p, [%1], %2;\n"
        " selp.b32 %0, 1, 0, p;\n}"
        : "=r"(done) : "r"(mbar), "r"(parity) : "memory");
    if (!done) {
        asm volatile(
            "{\n .reg .pred P1;\n"
            "WL_%=:\n"
            " mbarrier.try_wait.parity.acquire.cta.shared::cta.b64 P1, [%0], %1, 0x989680;\n"
            " @P1 bra.uni WD_%=;\n"
            " bra.uni WL_%=;\n"
            "WD_%=:\n}"
            :: "r"(mbar), "r"(parity) : "memory");
    }
}

#if HAS_TCGEN05
__device__ __forceinline__ uint32_t elect1() {
    uint32_t p;
    asm volatile("{\n .reg .pred p;\n elect.sync _|p, 0xFFFFFFFF;\n selp.b32 %0, 1, 0, p;\n}"
                 : "=r"(p));
    return p;
}
#define TC_ALLOC(smem_addr, ncols) \
    asm volatile("tcgen05.alloc.cta_group::1.sync.aligned.shared::cta.b32 [%0], %1;" \
                 :: "r"(smem_addr), "r"(ncols) : "memory")
#define TC_DEALLOC(tmem, ncols) \
    asm volatile("tcgen05.dealloc.cta_group::1.sync.aligned.b32 %0, %1;" \
                 :: "r"(tmem), "r"(ncols))
#define TC_RELINQ() \
    asm volatile("tcgen05.relinquish_alloc_permit.cta_group::1.sync.aligned;")
#define TC_COMMIT(mbar) \
    asm volatile("tcgen05.commit.cta_group::1.mbarrier::arrive::one.shared::cluster.b64 [%0];" \
                 :: "r"(mbar) : "memory")
#define TC_FENCE_AFTER()  asm volatile("tcgen05.fence::after_thread_sync;" ::: "memory")
#define TC_FENCE_BEFORE() asm volatile("tcgen05.fence::before_thread_sync;" ::: "memory")
#define TC_WAIT_LD()      asm volatile("tcgen05.wait::ld.sync.aligned;" ::: "memory")
#define TC_WAIT_ST()      asm volatile("tcgen05.wait::st.sync.aligned;" ::: "memory")

__device__ __forceinline__ void mma_ss(uint32_t d, uint64_t ad, uint64_t bd,
                                       uint32_t idesc, uint32_t en) {
    asm volatile(
        "{\n .reg .pred p;\n setp.ne.u32 p, %4, 0;\n"
        " tcgen05.mma.cta_group::1.kind::f16 [%0], %1, %2, %3, {%5, %5, %5, %5}, p;\n}"
        :: "r"(d), "l"(ad), "l"(bd), "r"(idesc), "r"(en), "r"(0u) : "memory");
}
__device__ __forceinline__ void mma_ts(uint32_t d, uint32_t a, uint64_t bd,
                                       uint32_t idesc, uint32_t en) {
    asm volatile(
        "{\n .reg .pred p;\n setp.ne.u32 p, %4, 0;\n"
        " tcgen05.mma.cta_group::1.kind::f16 [%0], [%1], %2, %3, {%5, %5, %5, %5}, p;\n}"
        :: "r"(d), "r"(a), "l"(bd), "r"(idesc), "r"(en), "r"(0u) : "memory");
}
__device__ __forceinline__ uint64_t make_desc(uint32_t addr) {
    return (uint64_t(2) << 61) | (uint64_t(1) << 46) | (uint64_t(64) << 32) |
           (uint64_t(1) << 16) | ((uint64_t)(addr >> 4) & 0x3FFF);
}

#define LDTM_X32(r, addr) \
    asm volatile( \
        "tcgen05.ld.sync.aligned.32x32b.x32.b32 " \
        "{%0, %1, %2, %3, %4, %5, %6, %7, " \
        " %8, %9, %10, %11, %12, %13, %14, %15, " \
        " %16, %17, %18, %19, %20, %21, %22, %23, " \
        " %24, %25, %26, %27, %28, %29, %30, %31}, [%32];" \
        : "=r"((r)[0]),  "=r"((r)[1]),  "=r"((r)[2]),  "=r"((r)[3]), \
          "=r"((r)[4]),  "=r"((r)[5]),  "=r"((r)[6]),  "=r"((r)[7]), \
          "=r"((r)[8]),  "=r"((r)[9]),  "=r"((r)[10]), "=r"((r)[11]), \
          "=r"((r)[12]), "=r"((r)[13]), "=r"((r)[14]), "=r"((r)[15]), \
          "=r"((r)[16]), "=r"((r)[17]), "=r"((r)[18]), "=r"((r)[19]), \
          "=r"((r)[20]), "=r"((r)[21]), "=r"((r)[22]), "=r"((r)[23]), \
          "=r"((r)[24]), "=r"((r)[25]), "=r"((r)[26]), "=r"((r)[27]), \
          "=r"((r)[28]), "=r"((r)[29]), "=r"((r)[30]), "=r"((r)[31]) \
        : "r"(addr))

#define STTM_X32(addr, r) \
    asm volatile( \
        "tcgen05.st.sync.aligned.32x32b.x32.b32 [%0], " \
        "{%1, %2, %3, %4, %5, %6, %7, %8, " \
        " %9, %10, %11, %12, %13, %14, %15, %16, " \
        " %17, %18, %19, %20, %21, %22, %23, %24, " \
        " %25, %26, %27, %28, %29, %30, %31, %32};" \
        :: "r"(addr), \
           "r"((r)[0]),  "r"((r)[1]),  "r"((r)[2]),  "r"((r)[3]), \
           "r"((r)[4]),  "r"((r)[5]),  "r"((r)[6]),  "r"((r)[7]), \
           "r"((r)[8]),  "r"((r)[9]),  "r"((r)[10]), "r"((r)[11]), \
           "r"((r)[12]), "r"((r)[13]), "r"((r)[14]), "r"((r)[15]), \
           "r"((r)[16]), "r"((r)[17]), "r"((r)[18]), "r"((r)[19]), \
           "r"((r)[20]), "r"((r)[21]), "r"((r)[22]), "r"((r)[23]), \
           "r"((r)[24]), "r"((r)[25]), "r"((r)[26]), "r"((r)[27]), \
           "r"((r)[28]), "r"((r)[29]), "r"((r)[30]), "r"((r)[31]) \
        : "memory")

#define STTM_X16(addr, r) \
    asm volatile( \
        "tcgen05.st.sync.aligned.32x32b.x16.b32 [%0], " \
        "{%1, %2, %3, %4, %5, %6, %7, %8, " \
        " %9, %10, %11, %12, %13, %14, %15, %16};" \
        :: "r"(addr), \
           "r"((r)[0]),  "r"((r)[1]),  "r"((r)[2]),  "r"((r)[3]), \
           "r"((r)[4]),  "r"((r)[5]),  "r"((r)[6]),  "r"((r)[7]), \
           "r"((r)[8]),  "r"((r)[9]),  "r"((r)[10]), "r"((r)[11]), \
           "r"((r)[12]), "r"((r)[13]), "r"((r)[14]), "r"((r)[15]) \
        : "memory")
#endif  // HAS_TCGEN05

// ---------------------------------------------------------------------------
// TMA-fed tensor-core GEMM, 128x256 tile, single-thread mainloop.
//   C = f( Ahi@Bhi^T + Alo@Bhi^T + Ahi@Blo^T ), A/B [2048,2048] bf16 row-major.
// Stage (96KB): Ahi 16K | Alo 16K | Bhi 32K | Blo 32K; 2-stage ring; SW128.
// Mainloop (round-10 proven): wait full -> 24x N=128 MMAs -> commit ->
// wait mma -> refill. The post-commit mma-wait throttles TMA to one
// outstanding fill, which measured FASTER than deferred-wait variants.
// ---------------------------------------------------------------------------
template <int MODE>
__global__ void __launch_bounds__(256) tma_gemm(
    const __grid_constant__ CUtensorMap tmAhi,
    const __grid_constant__ CUtensorMap tmAlo,
    const __grid_constant__ CUtensorMap tmBhi,
    const __grid_constant__ CUtensorMap tmBlo,
    const __nv_bfloat16* __restrict__ Ahi, const __nv_bfloat16* __restrict__ Alo,
    const __nv_bfloat16* __restrict__ Bhi, const __nv_bfloat16* __restrict__ Blo,
    float* __restrict__ Cf, __nv_bfloat16* __restrict__ Chi,
    __nv_bfloat16* __restrict__ Clo, float alpha)
{
    constexpr int NST = 2;
    constexpr int SBYTES = 98304;
    constexpr int NK = DIM / 64;       // 32

    extern __shared__ char dsm[];
    const int tid = threadIdx.x;
    const int wid = tid >> 5;
    const int lane = tid & 31;
    const int m0 = blockIdx.y * 128;
    const int n0 = blockIdx.x * 256;

    const uint32_t dbase = (cvta_smem(dsm) + 1023u) & ~1023u;
    float* sm = (float*)(((uintptr_t)dsm + 1023u) & ~(uintptr_t)1023u);

#if HAS_TCGEN05
    __shared__ uint64_t full_bar[NST];
    __shared__ uint64_t mma_bar[NST];
    __shared__ uint64_t end_bar;
    __shared__ uint32_t s_tptr;

    if (wid == 0) { TC_ALLOC(cvta_smem(&s_tptr), 256); TC_RELINQ(); }
    if (tid == 0) {
        for (int s = 0; s < NST; s++) {
            MBAR_INIT(cvta_smem(&full_bar[s]), 1);
            MBAR_INIT(cvta_smem(&mma_bar[s]), 1);
        }
        MBAR_INIT(cvta_smem(&end_bar), 1);
    }
    __syncthreads();
    const uint32_t tmem = s_tptr;
    const uint32_t idesc = (1u << 4) | (1u << 7) | (1u << 10) | (16u << 17) | (8u << 24);

    if (wid == 0 && elect1()) {
        auto issue_stage = [&](int kt, int s) {
            const uint32_t sb = dbase + s * SBYTES;
            const uint32_t fb = cvta_smem(&full_bar[s]);
            MBAR_EXPECT(fb, 98304u);
            tma2d(sb,         &tmAhi, kt * 64, m0, fb);
            tma2d(sb + 16384, &tmAlo, kt * 64, m0, fb);
            tma2d(sb + 32768, &tmBhi, kt * 64, n0, fb);
            tma2d(sb + 65536, &tmBlo, kt * 64, n0, fb);
        };
        issue_stage(0, 0);
        issue_stage(1, 1);

        int phf[NST] = {0, 0}, phm[NST] = {0, 0};
        int s = 0;
        for (int kt = 0; kt < NK; kt++) {
            mbar_wait(cvta_smem(&full_bar[s]), phf[s]); phf[s] ^= 1;
            const uint32_t sb = dbase + s * SBYTES;
#pragma unroll
            for (int t = 0; t < 3; t++) {
                const uint64_t ad = make_desc(sb + (t == 1 ? 16384 : 0));
                const uint32_t bb = sb + 32768 + (t == 2 ? 32768 : 0);
#pragma unroll
                for (int nh = 0; nh < 2; nh++) {
                    const uint64_t bd = make_desc(bb + nh * 16384);
#pragma unroll
                    for (int ki = 0; ki < 4; ki++)
                        mma_ss(tmem + nh * 128, ad + ki * 2, bd + ki * 2, idesc,
                               (kt | t | ki) != 0 ? 1u : 0u);
                }
            }
            TC_COMMIT(cvta_smem(&mma_bar[s]));
            if (kt + NST < NK) {
                mbar_wait(cvta_smem(&mma_bar[s]), phm[s]); phm[s] ^= 1;
                issue_stage(kt + NST, s);
            }
            s ^= 1;
        }
        TC_COMMIT(cvta_smem(&end_bar));
    }

    mbar_wait(cvta_smem(&end_bar), 0);
    TC_FENCE_AFTER();

    if (tid < 128) {
#pragma unroll
        for (int c = 0; c < 8; c++) {
            uint32_t r[32];
            LDTM_X32(r, tmem + c * 32);
            TC_WAIT_LD();
            float* dst = sm + (wid * 32 + lane) * 257 + c * 32;
#pragma unroll
            for (int j = 0; j < 32; j++) dst[j] = __uint_as_float(r[j]);
        }
        TC_FENCE_BEFORE();
    }
    __syncthreads();
    if (wid == 0) TC_DEALLOC(tmem, 256);

    for (int idx = tid; idx < 128 * 256; idx += 256) {
        const int r = idx >> 8, c = idx & 255;
        const float v = sm[r * 257 + c] * alpha;
        const long o = (long)(m0 + r) * DIM + (n0 + c);
        if (MODE == MODE_F32) Cf[o] = v;
        else {
            const __nv_bfloat16 h = __float2bfloat16(v);
            Chi[o] = h;
            Clo[o] = __float2bfloat16(v - __bfloat162float(h));
        }
    }
#else
    // Naive fallback (compile-only; the sm_103a cubin is selected at runtime).
    for (int idx = tid; idx < 128 * 256; idx += 256) {
        const int r = idx >> 8, c = idx & 255;
        float sum = 0.0f;
        for (int k = 0; k < DIM; k++) {
            const float a = __bfloat162float(Ahi[(long)(m0 + r) * DIM + k]) +
                            __bfloat162float(Alo[(long)(m0 + r) * DIM + k]);
            const float b = __bfloat162float(Bhi[(long)(n0 + c) * DIM + k]) +
                            __bfloat162float(Blo[(long)(n0 + c) * DIM + k]);
            sum += a * b;
        }
        const float v = sum * alpha;
        const long o = (long)(m0 + r) * DIM + (n0 + c);
        if (MODE == MODE_F32) Cf[o] = v;
        else {
            const __nv_bfloat16 h = __float2bfloat16(v);
            Chi[o] = h;
            Clo[o] = __float2bfloat16(v - __bfloat162float(h));
        }
    }
    (void)sm; (void)dbase;
#endif
}

// ---------------------------------------------------------------------------
// Split-K k/v projection (cp.async; 256 CTAs) — round-9 proven.
// ---------------------------------------------------------------------------
__global__ void __launch_bounds__(256) kv_gemm(
    const __nv_bfloat16* __restrict__ xhi, const __nv_bfloat16* __restrict__ xlo,
    const __nv_bfloat16* __restrict__ Wkhi, const __nv_bfloat16* __restrict__ Wklo,
    const __nv_bfloat16* __restrict__ Wvhi, const __nv_bfloat16* __restrict__ Wvlo,
    float* __restrict__ part)
{
    constexpr int NST = 3;
    constexpr int SBYTES = 65536;
    constexpr int KC = DIM / KSPLIT;
    extern __shared__ char dsm[];
    const int tid = threadIdx.x;
    const int wid = tid >> 5;
    const int lane = tid & 31;
    const int ks = blockIdx.x;
    const int m0 = blockIdx.y * 128;
    const int z = blockIdx.z;
    const long kOff = (long)ks * KC;

    const __nv_bfloat16* Bhi = z ? Wvhi : Wkhi;
    const __nv_bfloat16* Blo = z ? Wvlo : Wklo;
    float* out = part + ((long)z * KSPLIT + ks) * ((long)SEQ * HDIM) + (long)m0 * HDIM;

    const uint32_t dbase = (cvta_smem(dsm) + 1023u) & ~1023u;
    float* sm = (float*)(((uintptr_t)dsm + 1023u) & ~(uintptr_t)1023u);

    const int nk = KC / 64;

    auto load_stage = [&](int kt, int s) {
        const long k0 = kOff + (long)kt * 64;
        const uint32_t sb = dbase + s * SBYTES;
#pragma unroll
        for (int i = 0; i < 16; i++) {
            const int idx = tid + i * 256;
            const int partn = idx >> 10;
            const int r = (idx >> 3) & 127;
            const int c16 = idx & 7;
            const uint32_t off = r * 128 + c16 * 16;
            const uint32_t sw = off ^ ((off >> 3) & 0x70);
            const __nv_bfloat16* src;
            long grow;
            if (partn == 0)      { src = xhi; grow = (long)(m0 + r) * DIM; }
            else if (partn == 1) { src = xlo; grow = (long)(m0 + r) * DIM; }
            else if (partn == 2) { src = Bhi; grow = (long)r * DIM; }
            else                 { src = Blo; grow = (long)r * DIM; }
            cp16(sb + partn * 16384 + sw, src + grow + k0 + c16 * 8);
        }
        cp_commit();
    };

#if HAS_TCGEN05
    __shared__ uint64_t s_bar[NST + 1];
    __shared__ uint32_t s_tptr;

    if (wid == 0) { TC_ALLOC(cvta_smem(&s_tptr), 128); TC_RELINQ(); }
    if (tid == 0)
        for (int s = 0; s < NST + 1; s++) MBAR_INIT(cvta_smem(&s_bar[s]), 1);
    __syncthreads();
    const uint32_t tmem = s_tptr;

    for (int t = 0; t < NST; t++) load_stage(t, t);

    const uint32_t idesc = (1u << 4) | (1u << 7) | (1u << 10) | (16u << 17) | (8u << 24);
    int ph[NST];
#pragma unroll
    for (int s = 0; s < NST; s++) ph[s] = 0;

    int s = 0;
    for (int kt = 0; kt < nk; kt++) {
        cp_wait<NST - 1>();
        __syncthreads();
        asm volatile("fence.proxy.async.shared::cta;" ::: "memory");
        if (wid == 0) {
            if (elect1()) {
                const uint32_t sb = dbase + s * SBYTES;
#pragma unroll
                for (int t = 0; t < 3; t++) {
                    const uint64_t ad = make_desc(sb + (t == 1 ? 1 : 0) * 16384);
                    const uint64_t bd = make_desc(sb + (t == 2 ? 3 : 2) * 16384);
#pragma unroll
                    for (int ki = 0; ki < 4; ki++)
                        mma_ss(tmem, ad + ki * 2, bd + ki * 2, idesc,
                               (kt | t | ki) != 0 ? 1u : 0u);
                }
                TC_COMMIT(cvta_smem(&s_bar[s]));
            }
        }
        if (kt + NST < nk) {
            mbar_wait(cvta_smem(&s_bar[s]), ph[s]);
            ph[s] ^= 1;
            load_stage(kt + NST, s);
        } else {
            cp_commit();
        }
        s++; if (s == NST) s = 0;
    }

    if (wid == 0) { if (elect1()) TC_COMMIT(cvta_smem(&s_bar[NST])); }
    mbar_wait(cvta_smem(&s_bar[NST]), 0);
    TC_FENCE_AFTER();

    if (tid < 128) {
#pragma unroll
        for (int c = 0; c < 4; c++) {
            uint32_t r[32];
            LDTM_X32(r, tmem + c * 32);
            TC_WAIT_LD();
            float* dst = sm + (wid * 32 + lane) * 129 + c * 32;
#pragma unroll
            for (int j = 0; j < 32; j++) dst[j] = __uint_as_float(r[j]);
        }
        TC_FENCE_BEFORE();
    }
    __syncthreads();
    if (wid == 0) TC_DEALLOC(tmem, 128);

    for (int idx = tid; idx < 16384; idx += 256) {
        const int r = idx >> 7, c = idx & 127;
        out[(long)r * HDIM + c] = sm[r * 129 + c];
    }
#else
    for (int e = tid; e < 16384; e += 256) {
        const int r = e >> 7, c = e & 127;
        float sum = 0.0f;
        for (int kk = 0; kk < KC; kk++) {
            const long ik = kOff + kk;
            const float a = __bfloat162float(xhi[(long)(m0 + r) * DIM + ik]) +
                            __bfloat162float(xlo[(long)(m0 + r) * DIM + ik]);
            const float b = __bfloat162float(Bhi[(long)c * DIM + ik]) +
                            __bfloat162float(Blo[(long)c * DIM + ik]);
            sum += a * b;
        }
        out[(long)r * HDIM + c] = sum;
    }
#endif
}

// ---------------------------------------------------------------------------
__global__ void __launch_bounds__(256) kv_reduce(
    const float* __restrict__ part,
    __nv_bfloat16* __restrict__ khi, __nv_bfloat16* __restrict__ klo,
    __nv_bfloat16* __restrict__ vThi, __nv_bfloat16* __restrict__ vTlo)
{
    const long idx = (long)blockIdx.x * 256 + threadIdx.x;
    const int sel = (int)(idx >> 18);
    const long i = idx & 262143;
    const float* p = part + (long)sel * KSPLIT * SEQ * HDIM + i;
    float sum = 0.0f;
#pragma unroll
    for (int s = 0; s < KSPLIT; s++) sum += p[(long)s * SEQ * HDIM];
    const __nv_bfloat16 h = __float2bfloat16(sum);
    const __nv_bfloat16 l = __float2bfloat16(sum - __bfloat162float(h));
    if (sel == 0) {
        khi[i] = h; klo[i] = l;
    } else {
        const long m = i >> 7, c = i & 127;
        vThi[c * SEQ + m] = h; vTlo[c * SEQ + m] = l;
    }
}

// ---------------------------------------------------------------------------
// Fused flash attention per (head, q-tile 128) — round-8 proven.
// ---------------------------------------------------------------------------
__global__ void __launch_bounds__(256) fused_attn(
    const __nv_bfloat16* __restrict__ qhi, const __nv_bfloat16* __restrict__ qlo,
    const __nv_bfloat16* __restrict__ khi, const __nv_bfloat16* __restrict__ klo,
    const __nv_bfloat16* __restrict__ vThi, const __nv_bfloat16* __restrict__ vTlo,
    __nv_bfloat16* __restrict__ ohi, __nv_bfloat16* __restrict__ olo)
{
    extern __shared__ char dsm[];
    const int tid = threadIdx.x;
    const int wid = tid >> 5;
    const int lane = tid & 31;
    const int h = blockIdx.x;
    const int m0 = blockIdx.y * 128;
    const float scale = 0.08838834764831845f;
    const float CSH = 6.0f;

#if HAS_TCGEN05
    __shared__ uint64_t s_bar[2];
    __shared__ uint32_t s_tptr;
    __shared__ float rs[128];
    const uint32_t dbase = (cvta_smem(dsm) + 1023u) & ~1023u;

    if (wid == 0) { TC_ALLOC(cvta_smem(&s_tptr), 512); TC_RELINQ(); }
    if (tid == 0) { MBAR_INIT(cvta_smem(&s_bar[0]), 1); MBAR_INIT(cvta_smem(&s_bar[1]), 1); }
    if (tid < 128) rs[tid] = 0.0f;
    __syncthreads();
    const uint32_t tmem = s_tptr;
    const uint32_t tQ = tmem;
    const uint32_t tP = tmem + 128;
    const uint32_t tS = tmem + 256;
    const uint32_t tO = tmem + 384;

    const int sp = wid & 3;
    const int half = wid >> 2;
    const uint32_t woff = (uint32_t)sp << 21;

    auto load_k = [&](int j) {
#pragma unroll
        for (int i = 0; i < 16; i++) {
            const int idx = tid + i * 256;
            const int part = idx >> 10;
            const int r = (idx >> 3) & 127;
            const int c16 = idx & 7;
            const __nv_bfloat16* src = (part < 2) ? khi : klo;
            const uint32_t off = r * 128 + c16 * 16;
            cp16(dbase + part * 16384 + (off ^ ((off >> 3) & 0x70)),
                 src + (long)(j * 128 + r) * HDIM + (part & 1) * 64 + c16 * 8);
        }
        cp_commit();
    };
    auto load_v = [&](int j, int b) {
#pragma unroll
        for (int i = 0; i < 16; i++) {
            const int idx = tid + i * 256;
            const int part = idx >> 10;
            const int r = (idx >> 3) & 127;
            const int c16 = idx & 7;
            const __nv_bfloat16* src = (part < 2) ? vThi : vTlo;
            const uint32_t off = r * 128 + c16 * 16;
            cp16(dbase + 65536 + b * 65536 + part * 16384 + (off ^ ((off >> 3) & 0x70)),
                 src + (long)r * SEQ + j * 128 + (part & 1) * 64 + c16 * 8);
        }
        cp_commit();
    };

    load_k(0);
    load_v(0, 0);

    float rowsum = 0.0f;
    if (tid < 128) {
        const uint32_t qoff = (uint32_t)wid << 21;
        const uint4* s4h = (const uint4*)(qhi + (long)(m0 + tid) * DIM + h * HDIM);
        const uint4* s4l = (const uint4*)(qlo + (long)(m0 + tid) * DIM + h * HDIM);
        uint32_t rq[32];
#pragma unroll
        for (int hf = 0; hf < 2; hf++) {
#pragma unroll
            for (int i = 0; i < 8; i++) {
                uint4 t4 = s4h[hf * 8 + i];
                rq[i * 4] = t4.x; rq[i * 4 + 1] = t4.y; rq[i * 4 + 2] = t4.z; rq[i * 4 + 3] = t4.w;
            }
            STTM_X32(tQ + hf * 32 + qoff, rq);
        }
#pragma unroll
        for (int hf = 0; hf < 2; hf++) {
#pragma unroll
            for (int i = 0; i < 8; i++) {
                uint4 t4 = s4l[hf * 8 + i];
                rq[i * 4] = t4.x; rq[i * 4 + 1] = t4.y; rq[i * 4 + 2] = t4.z; rq[i * 4 + 3] = t4.w;
            }
            STTM_X32(tQ + 64 + hf * 32 + qoff, rq);
        }
        TC_WAIT_ST();
        TC_FENCE_BEFORE();
    }
    __syncthreads();

    const uint32_t idesc = (1u << 4) | (1u << 7) | (1u << 10) | (16u << 17) | (8u << 24);
    int ph_s = 0, ph_pv = 0;

    for (int j = 0; j < 16; j++) {
        cp_wait<0>();
        __syncthreads();
        asm volatile("fence.proxy.async.shared::cta;" ::: "memory");

        if (wid == 0) {
            if (elect1()) {
                TC_FENCE_AFTER();
#pragma unroll
                for (int t = 0; t < 3; t++) {
                    const uint32_t aoff = (t == 1) ? 64u : 0u;
                    const int bpart = (t == 2) ? 1 : 0;
#pragma unroll
                    for (int c = 0; c < 2; c++) {
                        const uint64_t bd = make_desc(dbase + (bpart * 2 + c) * 16384);
#pragma unroll
                        for (int ki = 0; ki < 4; ki++)
                            mma_ts(tS, tQ + aoff + c * 32 + ki * 8, bd + ki * 2, idesc,
                                   (t | c | ki) != 0 ? 1u : 0u);
                    }
                }
                TC_COMMIT(cvta_smem(&s_bar[0]));
            }
        }

        if (j > 0) { mbar_wait(cvta_smem(&s_bar[1]), ph_pv); ph_pv ^= 1; }
        if (j + 1 < 16) load_v(j + 1, (j + 1) & 1);

        mbar_wait(cvta_smem(&s_bar[0]), ph_s); ph_s ^= 1;
        TC_FENCE_AFTER();

        {
#pragma unroll
            for (int ss = 0; ss < 2; ss++) {
                const int slab = half * 2 + ss;
                uint32_t r[32];
                LDTM_X32(r, tS + slab * 32);
                TC_WAIT_LD();
                uint32_t phl[16], pll[16];
#pragma unroll
                for (int i = 0; i < 16; i++) {
                    const float e0 = __expf(__uint_as_float(r[2 * i]) * scale - CSH);
                    const float e1 = __expf(__uint_as_float(r[2 * i + 1]) * scale - CSH);
                    rowsum += e0 + e1;
                    const __nv_bfloat16 h0 = __float2bfloat16(e0);
                    const __nv_bfloat16 h1 = __float2bfloat16(e1);
                    const __nv_bfloat16 l0 = __float2bfloat16(e0 - __bfloat162float(h0));
                    const __nv_bfloat16 l1 = __float2bfloat16(e1 - __bfloat162float(h1));
                    __nv_bfloat162 hp(h0, h1), lp(l0, l1);
                    phl[i] = *(uint32_t*)&hp;
                    pll[i] = *(uint32_t*)&lp;
                }
                STTM_X16(tP + slab * 16 + woff, phl);
                STTM_X16(tP + 64 + slab * 16 + woff, pll);
            }
            TC_WAIT_ST();
            TC_FENCE_BEFORE();
        }
        __syncthreads();

        if (wid == 0) {
            if (elect1()) {
                TC_FENCE_AFTER();
                const uint32_t vb = dbase + 65536 + (j & 1) * 65536;
#pragma unroll
                for (int t = 0; t < 3; t++) {
                    const uint32_t aoff = (t == 1) ? 64u : 0u;
                    const int bpart = (t == 2) ? 1 : 0;
#pragma unroll
                    for (int c = 0; c < 2; c++) {
                        const uint64_t bd = make_desc(vb + (bpart * 2 + c) * 16384);
#pragma unroll
                        for (int ki = 0; ki < 4; ki++)
                            mma_ts(tO, tP + aoff + c * 32 + ki * 8, bd + ki * 2, idesc,
                                   (j | t | c | ki) != 0 ? 1u : 0u);
                    }
                }
                TC_COMMIT(cvta_smem(&s_bar[1]));
            }
        }
        if (j + 1 < 16) load_k(j + 1);
    }
    mbar_wait(cvta_smem(&s_bar[1]), ph_pv);
    TC_FENCE_AFTER();

    atomicAdd(&rs[sp * 32 + lane], rowsum);
    __syncthreads();

    {
        const float inv = 1.0f / rs[sp * 32 + lane];
        const long obase = (long)(m0 + sp * 32 + lane) * DIM + h * HDIM;
#pragma unroll
        for (int ss = 0; ss < 2; ss++) {
            const int slab = half * 2 + ss;
            uint32_t r[32];
            LDTM_X32(r, tO + slab * 32);
            TC_WAIT_LD();
            uint32_t hb[16], lb[16];
#pragma unroll
            for (int i = 0; i < 16; i++) {
                const float v0 = __uint_as_float(r[2 * i]) * inv;
                const float v1 = __uint_as_float(r[2 * i + 1]) * inv;
                const __nv_bfloat16 h0 = __float2bfloat16(v0);
                const __nv_bfloat16 h1 = __float2bfloat16(v1);
                const __nv_bfloat16 l0 = __float2bfloat16(v0 - __bfloat162float(h0));
                const __nv_bfloat16 l1 = __float2bfloat16(v1 - __bfloat162float(h1));
                __nv_bfloat162 hp(h0, h1), lp(l0, l1);
                hb[i] = *(uint32_t*)&hp;
                lb[i] = *(uint32_t*)&lp;
            }
            uint4* dh = (uint4*)(ohi + obase + slab * 32);
            uint4* dl = (uint4*)(olo + obase + slab * 32);
#pragma unroll
            for (int i = 0; i < 4; i++) {
                dh[i] = make_uint4(hb[4 * i], hb[4 * i + 1], hb[4 * i + 2], hb[4 * i + 3]);
                dl[i] = make_uint4(lb[4 * i], lb[4 * i + 1], lb[4 * i + 2], lb[4 * i + 3]);
            }
        }
    }
    __syncthreads();
    if (wid == 0) TC_DEALLOC(tmem, 512);

#else
    // fp32 fallback (compile-only)
    float* qsm = (float*)dsm;
    float* ksm = qsm + 16384;
    float* vsm = ksm + 16384;
    __shared__ float rsf[128];
    const int tr = tid >> 4, tc = tid & 15;
    float o[8][8];
#pragma unroll
    for (int i = 0; i < 8; i++)
#pragma unroll
        for (int j = 0; j < 8; j++) o[i][j] = 0.0f;
    if (tid < 128) rsf[tid] = 0.0f;

    for (int i = tid; i < 16384; i += 256) {
        const int r = i >> 7, c = i & 127;
        const long g = (long)(m0 + r) * DIM + h * HDIM + c;
        qsm[i] = __bfloat162float(qhi[g]) + __bfloat162float(qlo[g]);
    }
    __syncthreads();

    for (int j = 0; j < 16; j++) {
        for (int i = tid; i < 16384; i += 256) {
            const int r = i >> 7, c = i & 127;
            const long gk = (long)(j * 128 + r) * HDIM + c;
            ksm[i] = __bfloat162float(khi[gk]) + __bfloat162float(klo[gk]);
            const long gv = (long)c * SEQ + j * 128 + r;
            vsm[i] = __bfloat162float(vThi[gv]) + __bfloat162float(vTlo[gv]);
        }
        __syncthreads();
        float sacc[8][8];
#pragma unroll
        for (int i = 0; i < 8; i++)
#pragma unroll
            for (int j2 = 0; j2 < 8; j2++) sacc[i][j2] = 0.0f;
        for (int kk = 0; kk < 128; kk++) {
            float ar[8], br[8];
#pragma unroll
            for (int i = 0; i < 8; i++) ar[i] = qsm[(tr * 8 + i) * 128 + kk];
#pragma unroll
            for (int i = 0; i < 8; i++) br[i] = ksm[(tc * 8 + i) * 128 + kk];
#pragma unroll
            for (int i = 0; i < 8; i++)
#pragma unroll
                for (int j2 = 0; j2 < 8; j2++) sacc[i][j2] += ar[i] * br[j2];
        }
        __syncthreads();
#pragma unroll
        for (int i = 0; i < 8; i++) {
            float rl = 0.0f;
#pragma unroll
            for (int j2 = 0; j2 < 8; j2++) {
                const float p = __expf(sacc[i][j2] * scale - CSH);
                ksm[(tr * 8 + i) * 128 + tc * 8 + j2] = p;
                rl += p;
            }
            atomicAdd(&rsf[tr * 8 + i], rl);
        }
        __syncthreads();
        for (int kk = 0; kk < 128; kk++) {
            float pr[8], vr[8];
#pragma unroll
            for (int i = 0; i < 8; i++) pr[i] = ksm[(tr * 8 + i) * 128 + kk];
#pragma unroll
            for (int i = 0; i < 8; i++) vr[i] = vsm[kk * 128 + tc * 8 + i];
#pragma unroll
            for (int i = 0; i < 8; i++)
#pragma unroll
                for (int j2 = 0; j2 < 8; j2++) o[i][j2] += pr[i] * vr[j2];
        }
        __syncthreads();
    }
#pragma unroll
    for (int i = 0; i < 8; i++) {
        const int row = tr * 8 + i;
        const float inv = 1.0f / rsf[row];
#pragma unroll
        for (int j2 = 0; j2 < 8; j2++) {
            const float v = o[i][j2] * inv;
            const long g = (long)(m0 + row) * DIM + h * HDIM + tc * 8 + j2;
            const __nv_bfloat16 hh = __float2bfloat16(v);
            ohi[g] = hh;
            olo[g] = __float2bfloat16(v - __bfloat162float(hh));
        }
    }
#endif
}

// ---------------------------------------------------------------------------
__global__ void __launch_bounds__(256) split_all(
    const float* __restrict__ x,  const float* __restrict__ Wq,
    const float* __restrict__ Wk, const float* __restrict__ Wv,
    const float* __restrict__ Wo,
    __nv_bfloat16* __restrict__ xhi,  __nv_bfloat16* __restrict__ xlo,
    __nv_bfloat16* __restrict__ Wqhi, __nv_bfloat16* __restrict__ Wqlo,
    __nv_bfloat16* __restrict__ Wkhi, __nv_bfloat16* __restrict__ Wklo,
    __nv_bfloat16* __restrict__ Wvhi, __nv_bfloat16* __restrict__ Wvlo,
    __nv_bfloat16* __restrict__ Wohi, __nv_bfloat16* __restrict__ Wolo)
{
    const int bid = blockIdx.x;
    const float* src;
    __nv_bfloat16 *hi, *lo;
    long base;
    if (bid < 4096)      { src = x;  hi = xhi;  lo = xlo;  base = bid; }
    else if (bid < 8192) { src = Wq; hi = Wqhi; lo = Wqlo; base = bid - 4096; }
    else if (bid < 8448) { src = Wk; hi = Wkhi; lo = Wklo; base = bid - 8192; }
    else if (bid < 8704) { src = Wv; hi = Wvhi; lo = Wvlo; base = bid - 8448; }
    else                 { src = Wo; hi = Wohi; lo = Wolo; base = bid - 8704; }

    const long i = base * 256 + threadIdx.x;
    const float4 v = reinterpret_cast<const float4*>(src)[i];
    __nv_bfloat16 h0 = __float2bfloat16(v.x);
    __nv_bfloat16 h1 = __float2bfloat16(v.y);
    __nv_bfloat16 h2 = __float2bfloat16(v.z);
    __nv_bfloat16 h3 = __float2bfloat16(v.w);
    __nv_bfloat162* hi2 = reinterpret_cast<__nv_bfloat162*>(hi);
    __nv_bfloat162* lo2 = reinterpret_cast<__nv_bfloat162*>(lo);
    hi2[i * 2 + 0] = __nv_bfloat162(h0, h1);
    hi2[i * 2 + 1] = __nv_bfloat162(h2, h3);
    lo2[i * 2 + 0] = __nv_bfloat162(__float2bfloat16(v.x - __bfloat162float(h0)),
                                    __float2bfloat16(v.y - __bfloat162float(h1)));
    lo2[i * 2 + 1] = __nv_bfloat162(__float2bfloat16(v.z - __bfloat162float(h2)),
                                    __float2bfloat16(v.w - __bfloat162float(h3)));
}

// ---------------------------------------------------------------------------
typedef CUresult (*PFN_tmEncode)(
    CUtensorMap*, CUtensorMapDataType, cuuint32_t, void*,
    const cuuint64_t*, const cuuint64_t*, const cuuint32_t*, const cuuint32_t*,
    CUtensorMapInterleave, CUtensorMapSwizzle, CUtensorMapL2promotion,
    CUtensorMapFloatOOBfill);

static void make_tm(PFN_tmEncode enc, CUtensorMap* tm, void* ptr, uint32_t boxRows) {
    cuuint64_t dims[2]    = {DIM, DIM};
    cuuint64_t strides[1] = {DIM * 2};
    cuuint32_t box[2]     = {64, boxRows};
    cuuint32_t es[2]      = {1, 1};
    enc(tm, CU_TENSOR_MAP_DATA_TYPE_BFLOAT16, 2, ptr, dims, strides, box, es,
        CU_TENSOR_MAP_INTERLEAVE_NONE, CU_TENSOR_MAP_SWIZZLE_128B,
        CU_TENSOR_MAP_L2_PROMOTION_L2_128B, CU_TENSOR_MAP_FLOAT_OOB_FILL_NONE);
}

extern "C" void kernel_launch(void* const* d_in, const int* in_sizes, int n_in,
                              void* d_out, int out_size)
{
    const float* x  = (const float*)d_in[0];
    const float* Wq = (const float*)d_in[1];
    const float* Wk = (const float*)d_in[2];
    const float* Wv = (const float*)d_in[3];
    const float* Wo = (const float*)d_in[4];
    float* out = (float*)d_out;

    __nv_bfloat16 *xhi, *xlo, *Wqhi, *Wqlo, *Wkhi, *Wklo, *Wvhi, *Wvlo, *Wohi, *Wolo;
    __nv_bfloat16 *qhi, *qlo, *khi, *klo, *vThi, *vTlo, *athi, *atlo;
    float* kvpart;
    cudaGetSymbolAddress((void**)&xhi, g_xhi);   cudaGetSymbolAddress((void**)&xlo, g_xlo);
    cudaGetSymbolAddress((void**)&Wqhi, g_Wqhi); cudaGetSymbolAddress((void**)&Wqlo, g_Wqlo);
    cudaGetSymbolAddress((void**)&Wkhi, g_Wkhi); cudaGetSymbolAddress((void**)&Wklo, g_Wklo);
    cudaGetSymbolAddress((void**)&Wvhi, g_Wvhi); cudaGetSymbolAddress((void**)&Wvlo, g_Wvlo);
    cudaGetSymbolAddress((void**)&Wohi, g_Wohi); cudaGetSymbolAddress((void**)&Wolo, g_Wolo);
    cudaGetSymbolAddress((void**)&qhi, g_qhi);   cudaGetSymbolAddress((void**)&qlo, g_qlo);
    cudaGetSymbolAddress((void**)&khi, g_khi);   cudaGetSymbolAddress((void**)&klo, g_klo);
    cudaGetSymbolAddress((void**)&vThi, g_vThi); cudaGetSymbolAddress((void**)&vTlo, g_vTlo);
    cudaGetSymbolAddress((void**)&athi, g_athi); cudaGetSymbolAddress((void**)&atlo, g_atlo);
    cudaGetSymbolAddress((void**)&kvpart, g_kvpart);

    void* encPtr = nullptr;
    cudaDriverEntryPointQueryResult st;
    cudaGetDriverEntryPoint("cuTensorMapEncodeTiled", &encPtr, cudaEnableDefault, &st);
    PFN_tmEncode enc = (PFN_tmEncode)encPtr;

    CUtensorMap tmXhi, tmXlo, tmWqhi, tmWqlo, tmAThi, tmATlo, tmWohi, tmWolo;
    make_tm(enc, &tmXhi,  xhi,  128);
    make_tm(enc, &tmXlo,  xlo,  128);
    make_tm(enc, &tmWqhi, Wqhi, 256);
    make_tm(enc, &tmWqlo, Wqlo, 256);
    make_tm(enc, &tmAThi, athi, 128);
    make_tm(enc, &tmATlo, atlo, 128);
    make_tm(enc, &tmWohi, Wohi, 256);
    make_tm(enc, &tmWolo, Wolo, 256);

    cudaFuncSetAttribute((void*)tma_gemm<MODE_HILO>, cudaFuncAttributeMaxDynamicSharedMemorySize, GDSMEM);
    cudaFuncSetAttribute((void*)tma_gemm<MODE_F32>,  cudaFuncAttributeMaxDynamicSharedMemorySize, GDSMEM);
    cudaFuncSetAttribute((void*)kv_gemm,    cudaFuncAttributeMaxDynamicSharedMemorySize, GDSMEM);
    cudaFuncSetAttribute((void*)fused_attn, cudaFuncAttributeMaxDynamicSharedMemorySize, FDSMEM);

    // 0) splits
    split_all<<<12800, 256>>>(x, Wq, Wk, Wv, Wo,
                              xhi, xlo, Wqhi, Wqlo, Wkhi, Wklo,
                              Wvhi, Wvlo, Wohi, Wolo);

    // 1) k & vT projections (split-K) + reduce
    kv_gemm<<<dim3(KSPLIT, SEQ / 128, 2), 256, GDSMEM>>>(
        xhi, xlo, Wkhi, Wklo, Wvhi, Wvlo, kvpart);
    kv_reduce<<<2048, 256>>>(kvpart, khi, klo, vThi, vTlo);

    // 2) q = x @ Wq^T (TMA-fed)
    tma_gemm<MODE_HILO><<<dim3(DIM / 256, SEQ / 128), 256, GDSMEM>>>(
        tmXhi, tmXlo, tmWqhi, tmWqlo,
        xhi, xlo, Wqhi, Wqlo,
        nullptr, qhi, qlo, 1.0f);

    // 3) fused attention
    fused_attn<<<dim3(NHEADS, SEQ / 128), 256, FDSMEM>>>(
        qhi, qlo, khi, klo, vThi, vTlo, athi, atlo);

    // 4) out = attn @ Wo^T (TMA-fed)
    tma_gemm<MODE_F32><<<dim3(DIM / 256, SEQ / 128), 256, GDSMEM>>>(
        tmAThi, tmATlo, tmWohi, tmWolo,
        athi, atlo, Wohi, Wolo,
        out, nullptr, nullptr, 1.0f);
}